// round 1
// baseline (speedup 1.0000x reference)
#include <cuda_runtime.h>

typedef unsigned long long ull;

#define E_THREADS 128
#define M_FLOATS (64*320)
#define W1_FLOATS (64*16)

__device__ float g_M[M_FLOATS];     // [m][320]  folded W2 blocks
__device__ float g_W1t[W1_FLOATS];  // [m][16]   W1 transposed / 4

__device__ __forceinline__ ull pk2(float a, float b){ ull r; asm("mov.b64 %0, {%1,%2};" : "=l"(r) : "f"(a), "f"(b)); return r; }
__device__ __forceinline__ ull fma2(ull a, ull b, ull c){ ull d; asm("fma.rn.f32x2 %0, %1, %2, %3;" : "=l"(d) : "l"(a), "l"(b), "l"(c)); return d; }
__device__ __forceinline__ ull mul2(ull a, ull b){ ull d; asm("mul.rn.f32x2 %0, %1, %2;" : "=l"(d) : "l"(a), "l"(b)); return d; }
__device__ __forceinline__ float2 upk(ull a){ float2 f; asm("mov.b64 {%0,%1}, %2;" : "=f"(f.x), "=f"(f.y) : "l"(a)); return f; }

// ---------------- prep: fold W2 (+all scale constants) into M, transpose W1 ----------------
__global__ void prep_kernel(const float* __restrict__ W1, const float* __restrict__ W2)
{
    int idx = blockIdx.x * blockDim.x + threadIdx.x;
    const float a0  = 0.17677669529663687f;   // 1/sqrt(32)
    const float a1  = 0.27386127875258304f;   // sqrt(3/40)
    const float a1s = 0.15811388300841897f;   // sqrt(1/40)  (a1/sqrt(3))
    const float aE  = 0.33541019662496846f;   // a1*sqrt(1.5) = 3/sqrt(80)
    if (idx < M_FLOATS) {
        int m = idx / 320, o = idx % 320;
        int sect = o >> 6, r = o & 63, u = r >> 3, w = r & 7;
        const float* Vm = W2 + m * 576;
        float val;
        if (sect < 4) {
            int t0 = sect * 128 + u * 16 + w;
            float s = (sect <= 1) ? a0 : (sect == 2 ? a1 : a1s);
            val = s * 0.125f * (Vm[t0] + Vm[t0 + 8]);
        } else {
            val = aE * 0.125f * Vm[512 + u * 8 + w];
        }
        g_M[m * 320 + o] = val;
    }
    if (idx < W1_FLOATS) {
        int m = idx >> 4, j = idx & 15;
        g_W1t[m * 16 + j] = W1[j * 64 + m] * 0.25f;
    }
}

__global__ void zero_kernel(float* __restrict__ out, int n)
{
    int i = blockIdx.x * blockDim.x + threadIdx.x;
    if (i < n) out[i] = 0.0f;
}

__global__ void finish_kernel(float* __restrict__ out, int N)
{
    int i = blockIdx.x * blockDim.x + threadIdx.x;
    if (i < N * 8) {
        int node = i >> 3, c = i & 7;
        float v = out[node * 32 + c];
        out[node * 32 + c] = v / (1.0f + __expf(-v));
    }
}

// ---------------- main fused edge kernel ----------------
__global__ void __launch_bounds__(E_THREADS, 2) edge_kernel(
    const float* __restrict__ x, const float* __restrict__ pos,
    const int* __restrict__ ei, int E, float* __restrict__ out)
{
    extern __shared__ float sm[];
    float* smM  = sm;               // 64*320
    float* smW1 = sm + M_FLOATS;    // 64*16
    for (int i = threadIdx.x; i < M_FLOATS; i += E_THREADS) smM[i] = g_M[i];
    for (int i = threadIdx.x; i < W1_FLOATS; i += E_THREADS) smW1[i] = g_W1t[i];
    __syncthreads();

    int e = blockIdx.x * E_THREADS + threadIdx.x;
    if (e >= E) return;

    int r = ei[e];
    int c = ei[E + e];

    float evx = pos[3*r]   - pos[3*c];
    float evy = pos[3*r+1] - pos[3*c+1];
    float evz = pos[3*r+2] - pos[3*c+2];
    float d2  = evx*evx + evy*evy + evz*evz + 1e-12f;
    float d   = sqrtf(d2);
    float inv = 1.0f / d;
    float nx = evx*inv, ny = evy*inv, nz = evz*inv;

    // RBF basis (mu_j = j/3, delta = 1/3)
    float rb[16];
    #pragma unroll
    for (int j = 0; j < 16; j++) {
        float t = d - (float)j * (1.0f/3.0f);
        rb[j] = __expf(-4.5f * t * t);
    }

    // node features of the source node
    float4 X[8];
    const float4* xp = (const float4*)(x + (size_t)r * 32);
    #pragma unroll
    for (int i = 0; i < 8; i++) X[i] = xp[i];
    float p[8] = {X[0].x,X[0].y,X[0].z,X[0].w,X[1].x,X[1].y,X[1].z,X[1].w};
    float xv[8][3];
    {
        const float* xf = (const float*)&X[2];
        #pragma unroll
        for (int u = 0; u < 8; u++)
            #pragma unroll
            for (int k = 0; k < 3; k++) xv[u][k] = xf[u*3+k];
    }
    float q[8];
    #pragma unroll
    for (int u = 0; u < 8; u++) q[u] = xv[u][0]*nx + xv[u][1]*ny + xv[u][2]*nz;

    ull nn0 = pk2(nx,nx), nn1 = pk2(ny,ny), nn2 = pk2(nz,nz);
    const ull THIRDN = pk2(-1.0f/3.0f, -1.0f/3.0f);

    ull outS[4]   = {0,0,0,0};
    ull outV[3][4] = {{0,0,0,0},{0,0,0,0},{0,0,0,0}};
    ull cn[4]     = {0,0,0,0};   // coefficient of the n_k outer-product (C + E terms)

    // m is processed in 4 chunks of 16 (epilogue is linear in beta, so
    // partial contractions accumulate correctly)
    for (int ch = 0; ch < 4; ch++) {
        const int m0 = ch * 16;

        // h[16] = relu(rbf @ W1/4) for this chunk
        float h[16];
        #pragma unroll
        for (int mm = 0; mm < 16; mm++) {
            const float4* wrow = (const float4*)(smW1 + (m0 + mm) * 16);
            float4 w0 = wrow[0], w1 = wrow[1], w2 = wrow[2], w3 = wrow[3];
            float acc0 = rb[0]*w0.x + rb[1]*w0.y + rb[2]*w0.z + rb[3]*w0.w;
            float acc1 = rb[4]*w1.x + rb[5]*w1.y + rb[6]*w1.z + rb[7]*w1.w;
            float acc2 = rb[8]*w2.x + rb[9]*w2.y + rb[10]*w2.z + rb[11]*w2.w;
            float acc3 = rb[12]*w3.x + rb[13]*w3.y + rb[14]*w3.z + rb[15]*w3.w;
            h[mm] = fmaxf((acc0 + acc1) + (acc2 + acc3), 0.0f);
        }

        #pragma unroll
        for (int u = 0; u < 8; u++) {
            ull acc[5][4];
            #pragma unroll
            for (int s5 = 0; s5 < 5; s5++)
                #pragma unroll
                for (int wp = 0; wp < 4; wp++) acc[s5][wp] = 0ULL;

            const float* base = smM + m0 * 320 + u * 8;
            #pragma unroll
            for (int mm = 0; mm < 16; mm++) {
                const float* rowp = base + mm * 320;
                ull hp = pk2(h[mm], h[mm]);
                #pragma unroll
                for (int s5 = 0; s5 < 5; s5++) {
                    ulonglong2 v0 = *(const ulonglong2*)(rowp + s5 * 64);
                    ulonglong2 v1 = *(const ulonglong2*)(rowp + s5 * 64 + 4);
                    acc[s5][0] = fma2(v0.x, hp, acc[s5][0]);
                    acc[s5][1] = fma2(v0.y, hp, acc[s5][1]);
                    acc[s5][2] = fma2(v1.x, hp, acc[s5][2]);
                    acc[s5][3] = fma2(v1.y, hp, acc[s5][3]);
                }
            }

            // epilogue for this u / chunk (all linear)
            ull pp  = pk2(p[u], p[u]);
            ull qq  = pk2(q[u], q[u]);
            ull xx0 = pk2(xv[u][0], xv[u][0]);
            ull xx1 = pk2(xv[u][1], xv[u][1]);
            ull xx2 = pk2(xv[u][2], xv[u][2]);
            ull e0  = mul2(xx0, THIRDN);
            ull e1  = mul2(xx1, THIRDN);
            ull e2  = mul2(xx2, THIRDN);
            #pragma unroll
            for (int wp = 0; wp < 4; wp++) {
                outS[wp]   = fma2(acc[0][wp], pp, outS[wp]);      // A: xs
                outS[wp]   = fma2(acc[1][wp], qq, outS[wp]);      // B: xv.n
                cn[wp]     = fma2(acc[2][wp], pp, cn[wp]);        // C: xs * n_k
                cn[wp]     = fma2(acc[4][wp], qq, cn[wp]);        // E: (xv.n) n_k part
                outV[0][wp] = fma2(acc[3][wp], xx0, outV[0][wp]); // D: xv_k
                outV[1][wp] = fma2(acc[3][wp], xx1, outV[1][wp]);
                outV[2][wp] = fma2(acc[3][wp], xx2, outV[2][wp]);
                outV[0][wp] = fma2(acc[4][wp], e0, outV[0][wp]);  // E: -xv_k/3 part
                outV[1][wp] = fma2(acc[4][wp], e1, outV[1][wp]);
                outV[2][wp] = fma2(acc[4][wp], e2, outV[2][wp]);
            }
        }
    }

    // outer product of accumulated n-coefficient with n
    #pragma unroll
    for (int wp = 0; wp < 4; wp++) {
        outV[0][wp] = fma2(cn[wp], nn0, outV[0][wp]);
        outV[1][wp] = fma2(cn[wp], nn1, outV[1][wp]);
        outV[2][wp] = fma2(cn[wp], nn2, outV[2][wp]);
    }

    // scatter-add into node accumulator (d_out)
    float* yrow = out + (size_t)r * 32;
    #pragma unroll
    for (int wp = 0; wp < 4; wp++) {
        float2 s = upk(outS[wp]);
        atomicAdd(yrow + wp*2,     s.x);
        atomicAdd(yrow + wp*2 + 1, s.y);
    }
    #pragma unroll
    for (int wp = 0; wp < 4; wp++) {
        #pragma unroll
        for (int k = 0; k < 3; k++) {
            float2 v = upk(outV[k][wp]);
            atomicAdd(yrow + 8 + (wp*2)*3   + k, v.x);
            atomicAdd(yrow + 8 + (wp*2+1)*3 + k, v.y);
        }
    }
}

extern "C" void kernel_launch(void* const* d_in, const int* in_sizes, int n_in,
                              void* d_out, int out_size)
{
    const float* x   = (const float*)d_in[0];
    const float* pos = (const float*)d_in[1];
    const int*   ei  = (const int*)d_in[2];
    const float* W1  = (const float*)d_in[3];
    const float* W2  = (const float*)d_in[4];
    float* out = (float*)d_out;

    int E = in_sizes[2] / 2;
    int N = in_sizes[1] / 3;

    prep_kernel<<<(M_FLOATS + 255) / 256, 256>>>(W1, W2);
    zero_kernel<<<(out_size + 255) / 256, 256>>>(out, out_size);

    size_t smem = (M_FLOATS + W1_FLOATS) * sizeof(float);
    static int smem_set = 0;
    // cudaFuncSetAttribute is idempotent host-side state, safe under capture
    cudaFuncSetAttribute(edge_kernel, cudaFuncAttributeMaxDynamicSharedMemorySize, (int)smem);
    (void)smem_set;

    edge_kernel<<<(E + E_THREADS - 1) / E_THREADS, E_THREADS, smem>>>(x, pos, ei, E, out);
    finish_kernel<<<(N * 8 + 255) / 256, 256>>>(out, N);
}

// round 2
// speedup vs baseline: 1.5921x; 1.5921x over previous
#include <cuda_runtime.h>

typedef unsigned long long ull;

#define E_THREADS 128
#define M_FLOATS (64*320)
#define W1_FLOATS (64*16)
#define N_NODES 25000

__device__ float g_M[M_FLOATS];     // [m][320]  folded W2 blocks
__device__ float g_W1t[W1_FLOATS];  // [m][16]   W1 transposed / 4
__device__ double g_acc[N_NODES * 32];  // high-precision segment-sum accumulator

__device__ __forceinline__ ull pk2(float a, float b){ ull r; asm("mov.b64 %0, {%1,%2};" : "=l"(r) : "f"(a), "f"(b)); return r; }
__device__ __forceinline__ ull fma2(ull a, ull b, ull c){ ull d; asm("fma.rn.f32x2 %0, %1, %2, %3;" : "=l"(d) : "l"(a), "l"(b), "l"(c)); return d; }
__device__ __forceinline__ ull mul2(ull a, ull b){ ull d; asm("mul.rn.f32x2 %0, %1, %2;" : "=l"(d) : "l"(a), "l"(b)); return d; }
__device__ __forceinline__ float2 upk(ull a){ float2 f; asm("mov.b64 {%0,%1}, %2;" : "=f"(f.x), "=f"(f.y) : "l"(a)); return f; }

// ---------------- prep: fold W2 (+all scale constants) into M, transpose W1 ----------------
__global__ void prep_kernel(const float* __restrict__ W1, const float* __restrict__ W2)
{
    int idx = blockIdx.x * blockDim.x + threadIdx.x;
    const float a0  = 0.17677669529663687f;   // 1/sqrt(32)
    const float a1  = 0.27386127875258304f;   // sqrt(3/40)
    const float a1s = 0.15811388300841897f;   // sqrt(1/40)  (a1/sqrt(3))
    const float aE  = 0.33541019662496846f;   // a1*sqrt(1.5) = 3/sqrt(80)
    if (idx < M_FLOATS) {
        int m = idx / 320, o = idx % 320;
        int sect = o >> 6, r = o & 63, u = r >> 3, w = r & 7;
        const float* Vm = W2 + m * 576;
        float val;
        if (sect < 4) {
            int t0 = sect * 128 + u * 16 + w;
            float s = (sect <= 1) ? a0 : (sect == 2 ? a1 : a1s);
            val = s * 0.125f * (Vm[t0] + Vm[t0 + 8]);
        } else {
            val = aE * 0.125f * Vm[512 + u * 8 + w];
        }
        g_M[m * 320 + o] = val;
    }
    if (idx < W1_FLOATS) {
        int m = idx >> 4, j = idx & 15;
        g_W1t[m * 16 + j] = W1[j * 64 + m] * 0.25f;
    }
}

__global__ void zero_acc_kernel(int n)
{
    int i = blockIdx.x * blockDim.x + threadIdx.x;
    if (i < n) g_acc[i] = 0.0;
}

__global__ void finish_kernel(float* __restrict__ out, int N)
{
    int i = blockIdx.x * blockDim.x + threadIdx.x;
    if (i < N * 32) {
        int c = i & 31;
        float v = (float)g_acc[i];
        out[i] = (c < 8) ? (v / (1.0f + __expf(-v))) : v;
    }
}

// ---------------- main fused edge kernel ----------------
__global__ void __launch_bounds__(E_THREADS, 2) edge_kernel(
    const float* __restrict__ x, const float* __restrict__ pos,
    const int* __restrict__ ei, int E)
{
    extern __shared__ float sm[];
    float* smM  = sm;               // 64*320
    float* smW1 = sm + M_FLOATS;    // 64*16
    for (int i = threadIdx.x; i < M_FLOATS; i += E_THREADS) smM[i] = g_M[i];
    for (int i = threadIdx.x; i < W1_FLOATS; i += E_THREADS) smW1[i] = g_W1t[i];
    __syncthreads();

    int e = blockIdx.x * E_THREADS + threadIdx.x;
    if (e >= E) return;

    int r = ei[e];
    int c = ei[E + e];

    // node features of the source node (register-only: constant-index extraction,
    // NO address-taking of register arrays)
    const float4* xp = (const float4*)(x + (size_t)r * 32);
    float4 v0 = xp[0], v1 = xp[1], v2 = xp[2], v3 = xp[3];
    float4 v4 = xp[4], v5 = xp[5], v6 = xp[6], v7 = xp[7];

    float evx = pos[3*r]   - pos[3*c];
    float evy = pos[3*r+1] - pos[3*c+1];
    float evz = pos[3*r+2] - pos[3*c+2];
    float d2  = evx*evx + evy*evy + evz*evz + 1e-12f;
    float d   = sqrtf(d2);
    float inv = 1.0f / d;
    float nx = evx*inv, ny = evy*inv, nz = evz*inv;

    // RBF basis (mu_j = j/3, delta = 1/3)
    float rb[16];
    #pragma unroll
    for (int j = 0; j < 16; j++) {
        float t = d - (float)j * (1.0f/3.0f);
        rb[j] = __expf(-4.5f * t * t);
    }

    float p[8] = {v0.x,v0.y,v0.z,v0.w,v1.x,v1.y,v1.z,v1.w};
    float xv[8][3];
    xv[0][0]=v2.x; xv[0][1]=v2.y; xv[0][2]=v2.z;
    xv[1][0]=v2.w; xv[1][1]=v3.x; xv[1][2]=v3.y;
    xv[2][0]=v3.z; xv[2][1]=v3.w; xv[2][2]=v4.x;
    xv[3][0]=v4.y; xv[3][1]=v4.z; xv[3][2]=v4.w;
    xv[4][0]=v5.x; xv[4][1]=v5.y; xv[4][2]=v5.z;
    xv[5][0]=v5.w; xv[5][1]=v6.x; xv[5][2]=v6.y;
    xv[6][0]=v6.z; xv[6][1]=v6.w; xv[6][2]=v7.x;
    xv[7][0]=v7.y; xv[7][1]=v7.z; xv[7][2]=v7.w;

    float q[8];
    #pragma unroll
    for (int u = 0; u < 8; u++) q[u] = xv[u][0]*nx + xv[u][1]*ny + xv[u][2]*nz;

    ull nn0 = pk2(nx,nx), nn1 = pk2(ny,ny), nn2 = pk2(nz,nz);
    const ull THIRDN = pk2(-1.0f/3.0f, -1.0f/3.0f);

    ull outS[4]    = {0,0,0,0};
    ull outV[3][4] = {{0,0,0,0},{0,0,0,0},{0,0,0,0}};
    ull cn[4]      = {0,0,0,0};   // coefficient of the n_k outer-product (C + E terms)

    // m processed in 4 chunks of 16 (epilogue linear in beta -> partials accumulate)
    for (int ch = 0; ch < 4; ch++) {
        const int m0 = ch * 16;

        // hps[16] = packed relu(rbf @ W1/4) for this chunk
        ull hps[16];
        #pragma unroll
        for (int mm = 0; mm < 16; mm++) {
            const float4* wrow = (const float4*)(smW1 + (m0 + mm) * 16);
            float4 w0 = wrow[0], w1 = wrow[1], w2 = wrow[2], w3 = wrow[3];
            float acc0 = rb[0]*w0.x + rb[1]*w0.y + rb[2]*w0.z + rb[3]*w0.w;
            float acc1 = rb[4]*w1.x + rb[5]*w1.y + rb[6]*w1.z + rb[7]*w1.w;
            float acc2 = rb[8]*w2.x + rb[9]*w2.y + rb[10]*w2.z + rb[11]*w2.w;
            float acc3 = rb[12]*w3.x + rb[13]*w3.y + rb[14]*w3.z + rb[15]*w3.w;
            float h = fmaxf((acc0 + acc1) + (acc2 + acc3), 0.0f);
            hps[mm] = pk2(h, h);
        }

        #pragma unroll
        for (int u = 0; u < 8; u++) {
            ull acc[5][4];
            #pragma unroll
            for (int s5 = 0; s5 < 5; s5++)
                #pragma unroll
                for (int wp = 0; wp < 4; wp++) acc[s5][wp] = 0ULL;

            const float* base = smM + m0 * 320 + u * 8;
            #pragma unroll
            for (int mm = 0; mm < 16; mm++) {
                const float* rowp = base + mm * 320;
                ull hp = hps[mm];
                #pragma unroll
                for (int s5 = 0; s5 < 5; s5++) {
                    ulonglong2 t0 = *(const ulonglong2*)(rowp + s5 * 64);
                    ulonglong2 t1 = *(const ulonglong2*)(rowp + s5 * 64 + 4);
                    acc[s5][0] = fma2(t0.x, hp, acc[s5][0]);
                    acc[s5][1] = fma2(t0.y, hp, acc[s5][1]);
                    acc[s5][2] = fma2(t1.x, hp, acc[s5][2]);
                    acc[s5][3] = fma2(t1.y, hp, acc[s5][3]);
                }
            }

            // epilogue for this u / chunk (all linear)
            ull pp  = pk2(p[u], p[u]);
            ull qq  = pk2(q[u], q[u]);
            ull xx0 = pk2(xv[u][0], xv[u][0]);
            ull xx1 = pk2(xv[u][1], xv[u][1]);
            ull xx2 = pk2(xv[u][2], xv[u][2]);
            ull e0  = mul2(xx0, THIRDN);
            ull e1  = mul2(xx1, THIRDN);
            ull e2  = mul2(xx2, THIRDN);
            #pragma unroll
            for (int wp = 0; wp < 4; wp++) {
                outS[wp]    = fma2(acc[0][wp], pp, outS[wp]);     // A: xs
                outS[wp]    = fma2(acc[1][wp], qq, outS[wp]);     // B: xv.n
                cn[wp]      = fma2(acc[2][wp], pp, cn[wp]);       // C: xs * n_k
                cn[wp]      = fma2(acc[4][wp], qq, cn[wp]);       // E: (xv.n) n_k part
                outV[0][wp] = fma2(acc[3][wp], xx0, outV[0][wp]); // D: xv_k
                outV[1][wp] = fma2(acc[3][wp], xx1, outV[1][wp]);
                outV[2][wp] = fma2(acc[3][wp], xx2, outV[2][wp]);
                outV[0][wp] = fma2(acc[4][wp], e0, outV[0][wp]);  // E: -xv_k/3 part
                outV[1][wp] = fma2(acc[4][wp], e1, outV[1][wp]);
                outV[2][wp] = fma2(acc[4][wp], e2, outV[2][wp]);
            }
        }
    }

    // outer product of accumulated n-coefficient with n
    #pragma unroll
    for (int wp = 0; wp < 4; wp++) {
        outV[0][wp] = fma2(cn[wp], nn0, outV[0][wp]);
        outV[1][wp] = fma2(cn[wp], nn1, outV[1][wp]);
        outV[2][wp] = fma2(cn[wp], nn2, outV[2][wp]);
    }

    // scatter-add into high-precision node accumulator
    double* yrow = g_acc + (size_t)r * 32;
    #pragma unroll
    for (int wp = 0; wp < 4; wp++) {
        float2 s = upk(outS[wp]);
        atomicAdd(yrow + wp*2,     (double)s.x);
        atomicAdd(yrow + wp*2 + 1, (double)s.y);
    }
    #pragma unroll
    for (int wp = 0; wp < 4; wp++) {
        #pragma unroll
        for (int k = 0; k < 3; k++) {
            float2 v = upk(outV[k][wp]);
            atomicAdd(yrow + 8 + (wp*2)*3   + k, (double)v.x);
            atomicAdd(yrow + 8 + (wp*2+1)*3 + k, (double)v.y);
        }
    }
}

extern "C" void kernel_launch(void* const* d_in, const int* in_sizes, int n_in,
                              void* d_out, int out_size)
{
    const float* x   = (const float*)d_in[0];
    const float* pos = (const float*)d_in[1];
    const int*   ei  = (const int*)d_in[2];
    const float* W1  = (const float*)d_in[3];
    const float* W2  = (const float*)d_in[4];
    float* out = (float*)d_out;

    int E = in_sizes[2] / 2;
    int N = in_sizes[1] / 3;

    prep_kernel<<<(M_FLOATS + 255) / 256, 256>>>(W1, W2);
    zero_acc_kernel<<<(N * 32 + 255) / 256, 256>>>(N * 32);

    size_t smem = (M_FLOATS + W1_FLOATS) * sizeof(float);
    cudaFuncSetAttribute(edge_kernel, cudaFuncAttributeMaxDynamicSharedMemorySize, (int)smem);

    edge_kernel<<<(E + E_THREADS - 1) / E_THREADS, E_THREADS, smem>>>(x, pos, ei, E);
    finish_kernel<<<(N * 32 + 255) / 256, 256>>>(out, N);
}

// round 3
// speedup vs baseline: 1.6940x; 1.0640x over previous
#include <cuda_runtime.h>

typedef unsigned long long ull;

#define ETH 256
#define HTH 256
#define M_FLOATS (64*320)
#define W1_FLOATS (64*16)
#define N_NODES 25000
#define E_MAX 400000

__device__ float  g_M[M_FLOATS];              // [m][5 sect][8 u][8 w] folded weights
__device__ float  g_W1t[W1_FLOATS];           // [m][16] W1^T / 4
__device__ double g_acc[N_NODES * 32];        // segment-sum accumulator
__device__ float  g_hp[8][(size_t)E_MAX * 8]; // [chunk][e*8+mm] radial MLP outputs
__device__ float4 g_n[E_MAX];                 // unit edge vectors

__device__ __forceinline__ ull pk2(float a, float b){ ull r; asm("mov.b64 %0, {%1,%2};" : "=l"(r) : "f"(a), "f"(b)); return r; }
__device__ __forceinline__ ull fma2(ull a, ull b, ull c){ ull d; asm("fma.rn.f32x2 %0, %1, %2, %3;" : "=l"(d) : "l"(a), "l"(b), "l"(c)); return d; }
__device__ __forceinline__ float2 upk(ull a){ float2 f; asm("mov.b64 {%0,%1}, %2;" : "=f"(f.x), "=f"(f.y) : "l"(a)); return f; }

// ---------------- prep: fold W2 + scales into M (D section pre-folded with -E/3) ----------------
__global__ void prep_kernel(const float* __restrict__ W1, const float* __restrict__ W2)
{
    int idx = blockIdx.x * blockDim.x + threadIdx.x;
    const float a0  = 0.17677669529663687f;   // 1/sqrt(32)
    const float a1  = 0.27386127875258304f;   // sqrt(3/40)
    const float a1s = 0.15811388300841897f;   // a1/sqrt(3)
    const float aE  = 0.33541019662496846f;   // a1*sqrt(1.5)
    if (idx < M_FLOATS) {
        int m = idx / 320, o = idx % 320;
        int sect = o >> 6, r = o & 63, u = r >> 3, w = r & 7;
        const float* Vm = W2 + m * 576;
        float val;
        float eval = aE * 0.125f * Vm[512 + u * 8 + w];
        if (sect < 4) {
            int t0 = sect * 128 + u * 16 + w;
            float s = (sect <= 1) ? a0 : (sect == 2 ? a1 : a1s);
            val = s * 0.125f * (Vm[t0] + Vm[t0 + 8]);
            if (sect == 3) val -= eval * (1.0f / 3.0f);   // fold -E/3 into D
        } else {
            val = eval;
        }
        g_M[m * 320 + o] = val;
    }
    if (idx < W1_FLOATS) {
        int m = idx >> 4, j = idx & 15;
        g_W1t[m * 16 + j] = W1[j * 64 + m] * 0.25f;
    }
}

__global__ void zero_acc_kernel(int n)
{
    int i = blockIdx.x * blockDim.x + threadIdx.x;
    if (i < n) g_acc[i] = 0.0;
}

__global__ void finish_kernel(float* __restrict__ out, int N)
{
    int i = blockIdx.x * blockDim.x + threadIdx.x;
    if (i < N * 32) {
        int c = i & 31;
        float v = (float)g_acc[i];
        out[i] = (c < 8) ? (v / (1.0f + __expf(-v))) : v;
    }
}

// ---------------- radial MLP + edge geometry precompute ----------------
__global__ void h_kernel(const float* __restrict__ pos, const int* __restrict__ ei, int E)
{
    __shared__ float sW1[W1_FLOATS];
    for (int i = threadIdx.x; i < W1_FLOATS; i += HTH) sW1[i] = g_W1t[i];
    __syncthreads();

    int e = blockIdx.x * HTH + threadIdx.x;
    if (e >= E) return;

    int r = ei[e];
    int c = ei[E + e];
    float evx = pos[3*r]   - pos[3*c];
    float evy = pos[3*r+1] - pos[3*c+1];
    float evz = pos[3*r+2] - pos[3*c+2];
    float d2  = evx*evx + evy*evy + evz*evz + 1e-12f;
    float d   = sqrtf(d2);
    float inv = 1.0f / d;
    g_n[e] = make_float4(evx*inv, evy*inv, evz*inv, 0.0f);

    float rb[16];
    #pragma unroll
    for (int j = 0; j < 16; j++) {
        float t = d - (float)j * (1.0f/3.0f);
        rb[j] = __expf(-4.5f * t * t);
    }

    #pragma unroll 1
    for (int ch = 0; ch < 8; ch++) {
        float hb[8];
        #pragma unroll
        for (int mm = 0; mm < 8; mm++) {
            const float4* wrow = (const float4*)(sW1 + (ch*8 + mm) * 16);
            float4 w0 = wrow[0], w1 = wrow[1], w2 = wrow[2], w3 = wrow[3];
            float acc0 = rb[0]*w0.x + rb[1]*w0.y + rb[2]*w0.z + rb[3]*w0.w;
            float acc1 = rb[4]*w1.x + rb[5]*w1.y + rb[6]*w1.z + rb[7]*w1.w;
            float acc2 = rb[8]*w2.x + rb[9]*w2.y + rb[10]*w2.z + rb[11]*w2.w;
            float acc3 = rb[12]*w3.x + rb[13]*w3.y + rb[14]*w3.z + rb[15]*w3.w;
            hb[mm] = fmaxf((acc0 + acc1) + (acc2 + acc3), 0.0f);
        }
        float4* dst = (float4*)(g_hp[ch] + (size_t)e * 8);
        dst[0] = make_float4(hb[0], hb[1], hb[2], hb[3]);
        dst[1] = make_float4(hb[4], hb[5], hb[6], hb[7]);
    }
}

// ---------------- main fused edge kernel ----------------
__global__ void __launch_bounds__(ETH, 2) edge_kernel(
    const float* __restrict__ x, const int* __restrict__ ei, int E)
{
    extern __shared__ float smM[];
    #pragma unroll 1
    for (int i = threadIdx.x; i < M_FLOATS; i += ETH) smM[i] = g_M[i];
    __syncthreads();

    int e = blockIdx.x * ETH + threadIdx.x;
    if (e >= E) return;

    int r = ei[e];
    float4 nf = g_n[e];
    const float4* xp = (const float4*)(x + (size_t)r * 32);

    ull outS[4]    = {0,0,0,0};
    ull cn[4]      = {0,0,0,0};
    ull outV[3][4] = {{0,0,0,0},{0,0,0,0},{0,0,0,0}};

    #pragma unroll 1
    for (int pass = 0; pass < 2; pass++) {
        float4 pv = xp[pass];
        float pa[4] = {pv.x, pv.y, pv.z, pv.w};
        float4 A = xp[2 + pass*3], B = xp[3 + pass*3], C = xp[4 + pass*3];
        float xv[4][3];
        xv[0][0]=A.x; xv[0][1]=A.y; xv[0][2]=A.z;
        xv[1][0]=A.w; xv[1][1]=B.x; xv[1][2]=B.y;
        xv[2][0]=B.z; xv[2][1]=B.w; xv[2][2]=C.x;
        xv[3][0]=C.y; xv[3][1]=C.z; xv[3][2]=C.w;
        float qa[4];
        #pragma unroll
        for (int u = 0; u < 4; u++)
            qa[u] = xv[u][0]*nf.x + xv[u][1]*nf.y + xv[u][2]*nf.z;

        const float* mbase0 = smM + pass * 32;   // (pass*4+u)*8 = pass*32 + u*8

        #pragma unroll 1
        for (int ch = 0; ch < 8; ch++) {
            const float4* h4 = (const float4*)(g_hp[ch] + (size_t)e * 8);
            float4 h0 = h4[0], h1 = h4[1];
            ull hps[8];
            hps[0]=pk2(h0.x,h0.x); hps[1]=pk2(h0.y,h0.y); hps[2]=pk2(h0.z,h0.z); hps[3]=pk2(h0.w,h0.w);
            hps[4]=pk2(h1.x,h1.x); hps[5]=pk2(h1.y,h1.y); hps[6]=pk2(h1.z,h1.z); hps[7]=pk2(h1.w,h1.w);

            const float* mb = mbase0 + ch * 8 * 320;

            #pragma unroll
            for (int u = 0; u < 4; u++) {
                ull pp  = pk2(pa[u], pa[u]);
                ull qq  = pk2(qa[u], qa[u]);
                ull xx0 = pk2(xv[u][0], xv[u][0]);
                ull xx1 = pk2(xv[u][1], xv[u][1]);
                ull xx2 = pk2(xv[u][2], xv[u][2]);

                #pragma unroll
                for (int s5 = 0; s5 < 5; s5++) {
                    ull a0 = 0, a1 = 0, a2 = 0, a3 = 0;
                    #pragma unroll
                    for (int mm = 0; mm < 8; mm++) {
                        const float* rp = mb + mm * 320 + s5 * 64 + u * 8;
                        ulonglong2 t0 = *(const ulonglong2*)rp;
                        ulonglong2 t1 = *(const ulonglong2*)(rp + 4);
                        a0 = fma2(t0.x, hps[mm], a0);
                        a1 = fma2(t0.y, hps[mm], a1);
                        a2 = fma2(t1.x, hps[mm], a2);
                        a3 = fma2(t1.y, hps[mm], a3);
                    }
                    if (s5 == 0) {
                        outS[0]=fma2(a0,pp,outS[0]); outS[1]=fma2(a1,pp,outS[1]);
                        outS[2]=fma2(a2,pp,outS[2]); outS[3]=fma2(a3,pp,outS[3]);
                    } else if (s5 == 1) {
                        outS[0]=fma2(a0,qq,outS[0]); outS[1]=fma2(a1,qq,outS[1]);
                        outS[2]=fma2(a2,qq,outS[2]); outS[3]=fma2(a3,qq,outS[3]);
                    } else if (s5 == 2) {
                        cn[0]=fma2(a0,pp,cn[0]); cn[1]=fma2(a1,pp,cn[1]);
                        cn[2]=fma2(a2,pp,cn[2]); cn[3]=fma2(a3,pp,cn[3]);
                    } else if (s5 == 3) {   // D' (E's -xv/3 prefolded)
                        outV[0][0]=fma2(a0,xx0,outV[0][0]); outV[0][1]=fma2(a1,xx0,outV[0][1]);
                        outV[0][2]=fma2(a2,xx0,outV[0][2]); outV[0][3]=fma2(a3,xx0,outV[0][3]);
                        outV[1][0]=fma2(a0,xx1,outV[1][0]); outV[1][1]=fma2(a1,xx1,outV[1][1]);
                        outV[1][2]=fma2(a2,xx1,outV[1][2]); outV[1][3]=fma2(a3,xx1,outV[1][3]);
                        outV[2][0]=fma2(a0,xx2,outV[2][0]); outV[2][1]=fma2(a1,xx2,outV[2][1]);
                        outV[2][2]=fma2(a2,xx2,outV[2][2]); outV[2][3]=fma2(a3,xx2,outV[2][3]);
                    } else {               // E: q * n_k outer part
                        cn[0]=fma2(a0,qq,cn[0]); cn[1]=fma2(a1,qq,cn[1]);
                        cn[2]=fma2(a2,qq,cn[2]); cn[3]=fma2(a3,qq,cn[3]);
                    }
                }
            }
        }
    }

    // n outer-product on the accumulated coefficient
    ull nn0 = pk2(nf.x, nf.x), nn1 = pk2(nf.y, nf.y), nn2 = pk2(nf.z, nf.z);
    #pragma unroll
    for (int wp = 0; wp < 4; wp++) {
        outV[0][wp] = fma2(cn[wp], nn0, outV[0][wp]);
        outV[1][wp] = fma2(cn[wp], nn1, outV[1][wp]);
        outV[2][wp] = fma2(cn[wp], nn2, outV[2][wp]);
    }

    double* yrow = g_acc + (size_t)r * 32;
    #pragma unroll
    for (int wp = 0; wp < 4; wp++) {
        float2 s = upk(outS[wp]);
        atomicAdd(yrow + wp*2,     (double)s.x);
        atomicAdd(yrow + wp*2 + 1, (double)s.y);
    }
    #pragma unroll
    for (int wp = 0; wp < 4; wp++) {
        #pragma unroll
        for (int k = 0; k < 3; k++) {
            float2 v = upk(outV[k][wp]);
            atomicAdd(yrow + 8 + (wp*2)*3   + k, (double)v.x);
            atomicAdd(yrow + 8 + (wp*2+1)*3 + k, (double)v.y);
        }
    }
}

extern "C" void kernel_launch(void* const* d_in, const int* in_sizes, int n_in,
                              void* d_out, int out_size)
{
    const float* x   = (const float*)d_in[0];
    const float* pos = (const float*)d_in[1];
    const int*   ei  = (const int*)d_in[2];
    const float* W1  = (const float*)d_in[3];
    const float* W2  = (const float*)d_in[4];
    float* out = (float*)d_out;

    int E = in_sizes[2] / 2;
    int N = in_sizes[1] / 3;

    prep_kernel<<<(M_FLOATS + 255) / 256, 256>>>(W1, W2);
    zero_acc_kernel<<<(N * 32 + 255) / 256, 256>>>(N * 32);
    h_kernel<<<(E + HTH - 1) / HTH, HTH>>>(pos, ei, E);

    size_t smem = M_FLOATS * sizeof(float);
    cudaFuncSetAttribute(edge_kernel, cudaFuncAttributeMaxDynamicSharedMemorySize, (int)smem);
    edge_kernel<<<(E + ETH - 1) / ETH, ETH, smem>>>(x, ei, E);

    finish_kernel<<<(N * 32 + 255) / 256, 256>>>(out, N);
}

// round 4
// speedup vs baseline: 1.7799x; 1.0507x over previous
#include <cuda_runtime.h>

typedef unsigned long long ull;

#define ETH 128
#define HTH 256
#define M_FLOATS (64*320)
#define M1_FLOATS (64*256)
#define M2_FLOATS (64*64)
#define W1_FLOATS (64*16)
#define N_NODES 25000
#define E_MAX 400000

__device__ float  g_M1[M1_FLOATS];            // [m][sect4:{A,B,C,E}][u][w]
__device__ float  g_M2[M2_FLOATS];            // [m][u][w]  D' = D - E/3
__device__ float  g_W1t[W1_FLOATS];           // [m][16] W1^T / 4
__device__ double g_acc[N_NODES * 32];        // segment-sum accumulator
__device__ float  g_hp[8][(size_t)E_MAX * 8]; // [chunk][e*8+mm] radial MLP outputs
__device__ float4 g_n[E_MAX];                 // unit edge vectors

__device__ __forceinline__ ull pk2(float a, float b){ ull r; asm("mov.b64 %0, {%1,%2};" : "=l"(r) : "f"(a), "f"(b)); return r; }
__device__ __forceinline__ ull fma2(ull a, ull b, ull c){ ull d; asm("fma.rn.f32x2 %0, %1, %2, %3;" : "=l"(d) : "l"(a), "l"(b), "l"(c)); return d; }
__device__ __forceinline__ ull mul2(ull a, ull b){ ull d; asm("mul.rn.f32x2 %0, %1, %2;" : "=l"(d) : "l"(a), "l"(b)); return d; }
__device__ __forceinline__ float2 upk(ull a){ float2 f; asm("mov.b64 {%0,%1}, %2;" : "=f"(f.x), "=f"(f.y) : "l"(a)); return f; }

// ---------------- prep: fold W2 + scales into M1/M2 ----------------
__global__ void prep_kernel(const float* __restrict__ W1, const float* __restrict__ W2)
{
    int idx = blockIdx.x * blockDim.x + threadIdx.x;
    const float a0  = 0.17677669529663687f;   // 1/sqrt(32)
    const float a1  = 0.27386127875258304f;   // sqrt(3/40)
    const float a1s = 0.15811388300841897f;   // a1/sqrt(3)
    const float aE  = 0.33541019662496846f;   // a1*sqrt(1.5)
    if (idx < M_FLOATS) {
        int m = idx / 320, o = idx % 320;
        int sect = o >> 6, r = o & 63, u = r >> 3, w = r & 7;
        const float* Vm = W2 + m * 576;
        float eval = aE * 0.125f * Vm[512 + u * 8 + w];
        float val;
        if (sect < 4) {
            int t0 = sect * 128 + u * 16 + w;
            float s = (sect <= 1) ? a0 : (sect == 2 ? a1 : a1s);
            val = s * 0.125f * (Vm[t0] + Vm[t0 + 8]);
            if (sect == 3) val -= eval * (1.0f / 3.0f);   // fold -E/3 into D
        } else {
            val = eval;
        }
        if (sect == 3) {
            g_M2[m * 64 + u * 8 + w] = val;
        } else {
            int s4 = (sect == 4) ? 3 : sect;   // {A,B,C,E}
            g_M1[m * 256 + s4 * 64 + u * 8 + w] = val;
        }
    }
    if (idx < W1_FLOATS) {
        int m = idx >> 4, j = idx & 15;
        g_W1t[m * 16 + j] = W1[j * 64 + m] * 0.25f;
    }
}

__global__ void zero_acc_kernel(int n)
{
    int i = blockIdx.x * blockDim.x + threadIdx.x;
    if (i < n) g_acc[i] = 0.0;
}

__global__ void finish_kernel(float* __restrict__ out, int N)
{
    int i = blockIdx.x * blockDim.x + threadIdx.x;
    if (i < N * 32) {
        int c = i & 31;
        float v = (float)g_acc[i];
        out[i] = (c < 8) ? (v / (1.0f + __expf(-v))) : v;
    }
}

// ---------------- radial MLP + edge geometry precompute ----------------
__global__ void h_kernel(const float* __restrict__ pos, const int* __restrict__ ei, int E)
{
    __shared__ float sW1[W1_FLOATS];
    for (int i = threadIdx.x; i < W1_FLOATS; i += HTH) sW1[i] = g_W1t[i];
    __syncthreads();

    int e = blockIdx.x * HTH + threadIdx.x;
    if (e >= E) return;

    int r = ei[e];
    int c = ei[E + e];
    float evx = pos[3*r]   - pos[3*c];
    float evy = pos[3*r+1] - pos[3*c+1];
    float evz = pos[3*r+2] - pos[3*c+2];
    float d2  = evx*evx + evy*evy + evz*evz + 1e-12f;
    float d   = sqrtf(d2);
    float inv = 1.0f / d;
    g_n[e] = make_float4(evx*inv, evy*inv, evz*inv, 0.0f);

    float rb[16];
    #pragma unroll
    for (int j = 0; j < 16; j++) {
        float t = d - (float)j * (1.0f/3.0f);
        rb[j] = __expf(-4.5f * t * t);
    }

    #pragma unroll 1
    for (int ch = 0; ch < 8; ch++) {
        float hb[8];
        #pragma unroll
        for (int mm = 0; mm < 8; mm++) {
            const float4* wrow = (const float4*)(sW1 + (ch*8 + mm) * 16);
            float4 w0 = wrow[0], w1 = wrow[1], w2 = wrow[2], w3 = wrow[3];
            float acc0 = rb[0]*w0.x + rb[1]*w0.y + rb[2]*w0.z + rb[3]*w0.w;
            float acc1 = rb[4]*w1.x + rb[5]*w1.y + rb[6]*w1.z + rb[7]*w1.w;
            float acc2 = rb[8]*w2.x + rb[9]*w2.y + rb[10]*w2.z + rb[11]*w2.w;
            float acc3 = rb[12]*w3.x + rb[13]*w3.y + rb[14]*w3.z + rb[15]*w3.w;
            hb[mm] = fmaxf((acc0 + acc1) + (acc2 + acc3), 0.0f);
        }
        float4* dst = (float4*)(g_hp[ch] + (size_t)e * 8);
        dst[0] = make_float4(hb[0], hb[1], hb[2], hb[3]);
        dst[1] = make_float4(hb[4], hb[5], hb[6], hb[7]);
    }
}

// ---------------- main fused edge kernel: 2 edges / thread ----------------
__global__ void __launch_bounds__(ETH, 2) edge_kernel(
    const float* __restrict__ x, const int* __restrict__ ei, int E)
{
    extern __shared__ float sm[];
    float* smM1 = sm;               // 16384 floats
    float* smM2 = sm + M1_FLOATS;   // 4096 floats
    #pragma unroll 1
    for (int i = threadIdx.x; i < M1_FLOATS; i += ETH) smM1[i] = g_M1[i];
    #pragma unroll 1
    for (int i = threadIdx.x; i < M2_FLOATS; i += ETH) smM2[i] = g_M2[i];
    __syncthreads();

    int gid = blockIdx.x * ETH + threadIdx.x;
    int e0 = 2 * gid;
    if (e0 >= E) return;
    int e1 = e0 + 1;
    bool v1 = (e1 < E);
    int e1c = v1 ? e1 : e0;

    int r0 = ei[e0];
    int r1 = ei[e1c];
    float4 n0 = g_n[e0];
    float4 n1 = g_n[e1c];

    const float4* xp0 = (const float4*)(x + (size_t)r0 * 32);
    const float4* xp1 = (const float4*)(x + (size_t)r1 * 32);

    // scalar channels + q = xv.n for both edges
    float pa0[8], qa0[8], pa1[8], qa1[8];
    {
        float4 a = xp0[0], b = xp0[1];
        pa0[0]=a.x; pa0[1]=a.y; pa0[2]=a.z; pa0[3]=a.w;
        pa0[4]=b.x; pa0[5]=b.y; pa0[6]=b.z; pa0[7]=b.w;
        float4 A=xp0[2], B=xp0[3], C=xp0[4], D=xp0[5], Ee=xp0[6], F=xp0[7];
        qa0[0] = A.x*n0.x + A.y*n0.y + A.z*n0.z;
        qa0[1] = A.w*n0.x + B.x*n0.y + B.y*n0.z;
        qa0[2] = B.z*n0.x + B.w*n0.y + C.x*n0.z;
        qa0[3] = C.y*n0.x + C.z*n0.y + C.w*n0.z;
        qa0[4] = D.x*n0.x + D.y*n0.y + D.z*n0.z;
        qa0[5] = D.w*n0.x + Ee.x*n0.y + Ee.y*n0.z;
        qa0[6] = Ee.z*n0.x + Ee.w*n0.y + F.x*n0.z;
        qa0[7] = F.y*n0.x + F.z*n0.y + F.w*n0.z;
    }
    {
        float4 a = xp1[0], b = xp1[1];
        pa1[0]=a.x; pa1[1]=a.y; pa1[2]=a.z; pa1[3]=a.w;
        pa1[4]=b.x; pa1[5]=b.y; pa1[6]=b.z; pa1[7]=b.w;
        float4 A=xp1[2], B=xp1[3], C=xp1[4], D=xp1[5], Ee=xp1[6], F=xp1[7];
        qa1[0] = A.x*n1.x + A.y*n1.y + A.z*n1.z;
        qa1[1] = A.w*n1.x + B.x*n1.y + B.y*n1.z;
        qa1[2] = B.z*n1.x + B.w*n1.y + C.x*n1.z;
        qa1[3] = C.y*n1.x + C.z*n1.y + C.w*n1.z;
        qa1[4] = D.x*n1.x + D.y*n1.y + D.z*n1.z;
        qa1[5] = D.w*n1.x + Ee.x*n1.y + Ee.y*n1.z;
        qa1[6] = Ee.z*n1.x + Ee.w*n1.y + F.x*n1.z;
        qa1[7] = F.y*n1.x + F.z*n1.y + F.w*n1.z;
    }

    // ===== phase 1: sections A,B,C,E -> outS + cn =====
    ull outS0[4]={0,0,0,0}, outS1[4]={0,0,0,0};
    ull cn0[4]={0,0,0,0},   cn1[4]={0,0,0,0};

    #pragma unroll 1
    for (int ch = 0; ch < 8; ch++) {
        const float4* h40 = (const float4*)(g_hp[ch] + (size_t)e0 * 8);
        const float4* h41 = (const float4*)(g_hp[ch] + (size_t)e1c * 8);
        float4 ha = h40[0], hb = h40[1], hc = h41[0], hd = h41[1];
        ull hp0[8], hp1[8];
        hp0[0]=pk2(ha.x,ha.x); hp0[1]=pk2(ha.y,ha.y); hp0[2]=pk2(ha.z,ha.z); hp0[3]=pk2(ha.w,ha.w);
        hp0[4]=pk2(hb.x,hb.x); hp0[5]=pk2(hb.y,hb.y); hp0[6]=pk2(hb.z,hb.z); hp0[7]=pk2(hb.w,hb.w);
        hp1[0]=pk2(hc.x,hc.x); hp1[1]=pk2(hc.y,hc.y); hp1[2]=pk2(hc.z,hc.z); hp1[3]=pk2(hc.w,hc.w);
        hp1[4]=pk2(hd.x,hd.x); hp1[5]=pk2(hd.y,hd.y); hp1[6]=pk2(hd.z,hd.z); hp1[7]=pk2(hd.w,hd.w);

        const float* mb = smM1 + ch * 8 * 256;

        #pragma unroll
        for (int u = 0; u < 8; u++) {
            ull pp0 = pk2(pa0[u], pa0[u]);
            ull qq0 = pk2(qa0[u], qa0[u]);
            ull pp1 = pk2(pa1[u], pa1[u]);
            ull qq1 = pk2(qa1[u], qa1[u]);
            #pragma unroll
            for (int sect = 0; sect < 4; sect++) {
                ull a0=0,a1=0,a2=0,a3=0, b0=0,b1=0,b2=0,b3=0;
                #pragma unroll
                for (int mm = 0; mm < 8; mm++) {
                    const float* rp = mb + mm * 256 + sect * 64 + u * 8;
                    ulonglong2 t0 = *(const ulonglong2*)rp;
                    ulonglong2 t1 = *(const ulonglong2*)(rp + 4);
                    a0 = fma2(t0.x, hp0[mm], a0); a1 = fma2(t0.y, hp0[mm], a1);
                    a2 = fma2(t1.x, hp0[mm], a2); a3 = fma2(t1.y, hp0[mm], a3);
                    b0 = fma2(t0.x, hp1[mm], b0); b1 = fma2(t0.y, hp1[mm], b1);
                    b2 = fma2(t1.x, hp1[mm], b2); b3 = fma2(t1.y, hp1[mm], b3);
                }
                ull c0 = (sect & 1) ? qq0 : pp0;
                ull c1 = (sect & 1) ? qq1 : pp1;
                if (sect < 2) {
                    outS0[0]=fma2(a0,c0,outS0[0]); outS0[1]=fma2(a1,c0,outS0[1]);
                    outS0[2]=fma2(a2,c0,outS0[2]); outS0[3]=fma2(a3,c0,outS0[3]);
                    outS1[0]=fma2(b0,c1,outS1[0]); outS1[1]=fma2(b1,c1,outS1[1]);
                    outS1[2]=fma2(b2,c1,outS1[2]); outS1[3]=fma2(b3,c1,outS1[3]);
                } else {
                    cn0[0]=fma2(a0,c0,cn0[0]); cn0[1]=fma2(a1,c0,cn0[1]);
                    cn0[2]=fma2(a2,c0,cn0[2]); cn0[3]=fma2(a3,c0,cn0[3]);
                    cn1[0]=fma2(b0,c1,cn1[0]); cn1[1]=fma2(b1,c1,cn1[1]);
                    cn1[2]=fma2(b2,c1,cn1[2]); cn1[3]=fma2(b3,c1,cn1[3]);
                }
            }
        }
    }

    // scalar-output atomics (frees outS registers before phase 2)
    {
        double* y0 = g_acc + (size_t)r0 * 32;
        #pragma unroll
        for (int wp = 0; wp < 4; wp++) {
            float2 s = upk(outS0[wp]);
            atomicAdd(y0 + wp*2,     (double)s.x);
            atomicAdd(y0 + wp*2 + 1, (double)s.y);
        }
        if (v1) {
            double* y1 = g_acc + (size_t)r1 * 32;
            #pragma unroll
            for (int wp = 0; wp < 4; wp++) {
                float2 s = upk(outS1[wp]);
                atomicAdd(y1 + wp*2,     (double)s.x);
                atomicAdd(y1 + wp*2 + 1, (double)s.y);
            }
        }
    }

    // ===== phase 2: section D' -> outV, seeded with cn ⊗ n =====
    ull oV0[3][4], oV1[3][4];
    {
        ull nn;
        nn = pk2(n0.x, n0.x);
        oV0[0][0]=mul2(cn0[0],nn); oV0[0][1]=mul2(cn0[1],nn); oV0[0][2]=mul2(cn0[2],nn); oV0[0][3]=mul2(cn0[3],nn);
        nn = pk2(n0.y, n0.y);
        oV0[1][0]=mul2(cn0[0],nn); oV0[1][1]=mul2(cn0[1],nn); oV0[1][2]=mul2(cn0[2],nn); oV0[1][3]=mul2(cn0[3],nn);
        nn = pk2(n0.z, n0.z);
        oV0[2][0]=mul2(cn0[0],nn); oV0[2][1]=mul2(cn0[1],nn); oV0[2][2]=mul2(cn0[2],nn); oV0[2][3]=mul2(cn0[3],nn);
        nn = pk2(n1.x, n1.x);
        oV1[0][0]=mul2(cn1[0],nn); oV1[0][1]=mul2(cn1[1],nn); oV1[0][2]=mul2(cn1[2],nn); oV1[0][3]=mul2(cn1[3],nn);
        nn = pk2(n1.y, n1.y);
        oV1[1][0]=mul2(cn1[0],nn); oV1[1][1]=mul2(cn1[1],nn); oV1[1][2]=mul2(cn1[2],nn); oV1[1][3]=mul2(cn1[3],nn);
        nn = pk2(n1.z, n1.z);
        oV1[2][0]=mul2(cn1[0],nn); oV1[2][1]=mul2(cn1[1],nn); oV1[2][2]=mul2(cn1[2],nn); oV1[2][3]=mul2(cn1[3],nn);
    }

    #pragma unroll 1
    for (int pass = 0; pass < 2; pass++) {
        float4 A0 = xp0[2 + pass*3], B0 = xp0[3 + pass*3], C0 = xp0[4 + pass*3];
        float4 A1 = xp1[2 + pass*3], B1 = xp1[3 + pass*3], C1 = xp1[4 + pass*3];
        float xv0[4][3], xv1[4][3];
        xv0[0][0]=A0.x; xv0[0][1]=A0.y; xv0[0][2]=A0.z;
        xv0[1][0]=A0.w; xv0[1][1]=B0.x; xv0[1][2]=B0.y;
        xv0[2][0]=B0.z; xv0[2][1]=B0.w; xv0[2][2]=C0.x;
        xv0[3][0]=C0.y; xv0[3][1]=C0.z; xv0[3][2]=C0.w;
        xv1[0][0]=A1.x; xv1[0][1]=A1.y; xv1[0][2]=A1.z;
        xv1[1][0]=A1.w; xv1[1][1]=B1.x; xv1[1][2]=B1.y;
        xv1[2][0]=B1.z; xv1[2][1]=B1.w; xv1[2][2]=C1.x;
        xv1[3][0]=C1.y; xv1[3][1]=C1.z; xv1[3][2]=C1.w;

        #pragma unroll 1
        for (int ch = 0; ch < 8; ch++) {
            const float4* h40 = (const float4*)(g_hp[ch] + (size_t)e0 * 8);
            const float4* h41 = (const float4*)(g_hp[ch] + (size_t)e1c * 8);
            float4 ha = h40[0], hb = h40[1], hc = h41[0], hd = h41[1];
            ull hp0[8], hp1[8];
            hp0[0]=pk2(ha.x,ha.x); hp0[1]=pk2(ha.y,ha.y); hp0[2]=pk2(ha.z,ha.z); hp0[3]=pk2(ha.w,ha.w);
            hp0[4]=pk2(hb.x,hb.x); hp0[5]=pk2(hb.y,hb.y); hp0[6]=pk2(hb.z,hb.z); hp0[7]=pk2(hb.w,hb.w);
            hp1[0]=pk2(hc.x,hc.x); hp1[1]=pk2(hc.y,hc.y); hp1[2]=pk2(hc.z,hc.z); hp1[3]=pk2(hc.w,hc.w);
            hp1[4]=pk2(hd.x,hd.x); hp1[5]=pk2(hd.y,hd.y); hp1[6]=pk2(hd.z,hd.z); hp1[7]=pk2(hd.w,hd.w);

            const float* mb = smM2 + ch * 8 * 64 + pass * 32;

            #pragma unroll
            for (int u = 0; u < 4; u++) {
                ull a0=0,a1=0,a2=0,a3=0, b0=0,b1=0,b2=0,b3=0;
                #pragma unroll
                for (int mm = 0; mm < 8; mm++) {
                    const float* rp = mb + mm * 64 + u * 8;
                    ulonglong2 t0 = *(const ulonglong2*)rp;
                    ulonglong2 t1 = *(const ulonglong2*)(rp + 4);
                    a0 = fma2(t0.x, hp0[mm], a0); a1 = fma2(t0.y, hp0[mm], a1);
                    a2 = fma2(t1.x, hp0[mm], a2); a3 = fma2(t1.y, hp0[mm], a3);
                    b0 = fma2(t0.x, hp1[mm], b0); b1 = fma2(t0.y, hp1[mm], b1);
                    b2 = fma2(t1.x, hp1[mm], b2); b3 = fma2(t1.y, hp1[mm], b3);
                }
                #pragma unroll
                for (int k = 0; k < 3; k++) {
                    ull x0 = pk2(xv0[u][k], xv0[u][k]);
                    ull x1 = pk2(xv1[u][k], xv1[u][k]);
                    oV0[k][0]=fma2(a0,x0,oV0[k][0]); oV0[k][1]=fma2(a1,x0,oV0[k][1]);
                    oV0[k][2]=fma2(a2,x0,oV0[k][2]); oV0[k][3]=fma2(a3,x0,oV0[k][3]);
                    oV1[k][0]=fma2(b0,x1,oV1[k][0]); oV1[k][1]=fma2(b1,x1,oV1[k][1]);
                    oV1[k][2]=fma2(b2,x1,oV1[k][2]); oV1[k][3]=fma2(b3,x1,oV1[k][3]);
                }
            }
        }
    }

    // vector-output atomics
    {
        double* y0 = g_acc + (size_t)r0 * 32;
        #pragma unroll
        for (int wp = 0; wp < 4; wp++) {
            #pragma unroll
            for (int k = 0; k < 3; k++) {
                float2 v = upk(oV0[k][wp]);
                atomicAdd(y0 + 8 + (wp*2)*3   + k, (double)v.x);
                atomicAdd(y0 + 8 + (wp*2+1)*3 + k, (double)v.y);
            }
        }
        if (v1) {
            double* y1 = g_acc + (size_t)r1 * 32;
            #pragma unroll
            for (int wp = 0; wp < 4; wp++) {
                #pragma unroll
                for (int k = 0; k < 3; k++) {
                    float2 v = upk(oV1[k][wp]);
                    atomicAdd(y1 + 8 + (wp*2)*3   + k, (double)v.x);
                    atomicAdd(y1 + 8 + (wp*2+1)*3 + k, (double)v.y);
                }
            }
        }
    }
}

extern "C" void kernel_launch(void* const* d_in, const int* in_sizes, int n_in,
                              void* d_out, int out_size)
{
    const float* x   = (const float*)d_in[0];
    const float* pos = (const float*)d_in[1];
    const int*   ei  = (const int*)d_in[2];
    const float* W1  = (const float*)d_in[3];
    const float* W2  = (const float*)d_in[4];
    float* out = (float*)d_out;

    int E = in_sizes[2] / 2;
    int N = in_sizes[1] / 3;

    prep_kernel<<<(M_FLOATS + 255) / 256, 256>>>(W1, W2);
    zero_acc_kernel<<<(N * 32 + 255) / 256, 256>>>(N * 32);
    h_kernel<<<(E + HTH - 1) / HTH, HTH>>>(pos, ei, E);

    int pairs = (E + 1) / 2;
    int blocks = (pairs + ETH - 1) / ETH;
    size_t smem = (M1_FLOATS + M2_FLOATS) * sizeof(float);
    cudaFuncSetAttribute(edge_kernel, cudaFuncAttributeMaxDynamicSharedMemorySize, (int)smem);
    edge_kernel<<<blocks, ETH, smem>>>(x, ei, E);

    finish_kernel<<<(N * 32 + 255) / 256, 256>>>(out, N);
}

// round 5
// speedup vs baseline: 1.8062x; 1.0148x over previous
#include <cuda_runtime.h>

typedef unsigned long long ull;

#define ETH 128
#define HTH 256
#define M_FLOATS (64*320)
#define M1_FLOATS (64*256)
#define M2_FLOATS (64*64)
#define W1_FLOATS (64*16)
#define N_NODES 25000
#define E_MAX 400000

__device__ float  g_M1[M1_FLOATS];            // [m][sect4:{A,B,C,E}][u][w]
__device__ float  g_M2[M2_FLOATS];            // [m][u][w]  D' = D - E/3  (L1-resident, LDG)
__device__ float  g_W1t[W1_FLOATS];           // [m][16] W1^T / 4
__device__ double g_acc[N_NODES * 32];        // segment-sum accumulator
__device__ float  g_hp[8][(size_t)E_MAX * 8]; // [chunk][e*8+mm] radial MLP outputs
__device__ float4 g_n[E_MAX];                 // unit edge vectors

__device__ __forceinline__ ull pk2(float a, float b){ ull r; asm("mov.b64 %0, {%1,%2};" : "=l"(r) : "f"(a), "f"(b)); return r; }
__device__ __forceinline__ ull fma2(ull a, ull b, ull c){ ull d; asm("fma.rn.f32x2 %0, %1, %2, %3;" : "=l"(d) : "l"(a), "l"(b), "l"(c)); return d; }
__device__ __forceinline__ ull mul2(ull a, ull b){ ull d; asm("mul.rn.f32x2 %0, %1, %2;" : "=l"(d) : "l"(a), "l"(b)); return d; }
__device__ __forceinline__ float2 upk(ull a){ float2 f; asm("mov.b64 {%0,%1}, %2;" : "=f"(f.x), "=f"(f.y) : "l"(a)); return f; }

// ---------------- prep: fold W2 + scales into M1/M2 ----------------
__global__ void prep_kernel(const float* __restrict__ W1, const float* __restrict__ W2)
{
    int idx = blockIdx.x * blockDim.x + threadIdx.x;
    const float a0  = 0.17677669529663687f;   // 1/sqrt(32)
    const float a1  = 0.27386127875258304f;   // sqrt(3/40)
    const float a1s = 0.15811388300841897f;   // a1/sqrt(3)
    const float aE  = 0.33541019662496846f;   // a1*sqrt(1.5)
    if (idx < M_FLOATS) {
        int m = idx / 320, o = idx % 320;
        int sect = o >> 6, r = o & 63, u = r >> 3, w = r & 7;
        const float* Vm = W2 + m * 576;
        float eval = aE * 0.125f * Vm[512 + u * 8 + w];
        float val;
        if (sect < 4) {
            int t0 = sect * 128 + u * 16 + w;
            float s = (sect <= 1) ? a0 : (sect == 2 ? a1 : a1s);
            val = s * 0.125f * (Vm[t0] + Vm[t0 + 8]);
            if (sect == 3) val -= eval * (1.0f / 3.0f);   // fold -E/3 into D
        } else {
            val = eval;
        }
        if (sect == 3) {
            g_M2[m * 64 + u * 8 + w] = val;
        } else {
            int s4 = (sect == 4) ? 3 : sect;   // {A,B,C,E}
            g_M1[m * 256 + s4 * 64 + u * 8 + w] = val;
        }
    }
    if (idx < W1_FLOATS) {
        int m = idx >> 4, j = idx & 15;
        g_W1t[m * 16 + j] = W1[j * 64 + m] * 0.25f;
    }
}

__global__ void zero_acc_kernel(int n)
{
    int i = blockIdx.x * blockDim.x + threadIdx.x;
    if (i < n) g_acc[i] = 0.0;
}

__global__ void finish_kernel(float* __restrict__ out, int N)
{
    int i = blockIdx.x * blockDim.x + threadIdx.x;
    if (i < N * 32) {
        int c = i & 31;
        float v = (float)g_acc[i];
        out[i] = (c < 8) ? (v / (1.0f + __expf(-v))) : v;
    }
}

// ---------------- radial MLP + edge geometry precompute ----------------
__global__ void h_kernel(const float* __restrict__ pos, const int* __restrict__ ei, int E)
{
    __shared__ float sW1[W1_FLOATS];
    for (int i = threadIdx.x; i < W1_FLOATS; i += HTH) sW1[i] = g_W1t[i];
    __syncthreads();

    int e = blockIdx.x * HTH + threadIdx.x;
    if (e >= E) return;

    int r = ei[e];
    int c = ei[E + e];
    float evx = pos[3*r]   - pos[3*c];
    float evy = pos[3*r+1] - pos[3*c+1];
    float evz = pos[3*r+2] - pos[3*c+2];
    float d2  = evx*evx + evy*evy + evz*evz + 1e-12f;
    float d   = sqrtf(d2);
    float inv = 1.0f / d;
    g_n[e] = make_float4(evx*inv, evy*inv, evz*inv, 0.0f);

    float rb[16];
    #pragma unroll
    for (int j = 0; j < 16; j++) {
        float t = d - (float)j * (1.0f/3.0f);
        rb[j] = __expf(-4.5f * t * t);
    }

    #pragma unroll 1
    for (int ch = 0; ch < 8; ch++) {
        float hb[8];
        #pragma unroll
        for (int mm = 0; mm < 8; mm++) {
            const float4* wrow = (const float4*)(sW1 + (ch*8 + mm) * 16);
            float4 w0 = wrow[0], w1 = wrow[1], w2 = wrow[2], w3 = wrow[3];
            float acc0 = rb[0]*w0.x + rb[1]*w0.y + rb[2]*w0.z + rb[3]*w0.w;
            float acc1 = rb[4]*w1.x + rb[5]*w1.y + rb[6]*w1.z + rb[7]*w1.w;
            float acc2 = rb[8]*w2.x + rb[9]*w2.y + rb[10]*w2.z + rb[11]*w2.w;
            float acc3 = rb[12]*w3.x + rb[13]*w3.y + rb[14]*w3.z + rb[15]*w3.w;
            hb[mm] = fmaxf((acc0 + acc1) + (acc2 + acc3), 0.0f);
        }
        float4* dst = (float4*)(g_hp[ch] + (size_t)e * 8);
        dst[0] = make_float4(hb[0], hb[1], hb[2], hb[3]);
        dst[1] = make_float4(hb[4], hb[5], hb[6], hb[7]);
    }
}

// ---------------- main fused edge kernel: 2 edges / thread, 3 CTAs/SM ----------------
__global__ void __launch_bounds__(ETH, 3) edge_kernel(
    const float* __restrict__ x, const int* __restrict__ ei, int E)
{
    extern __shared__ float smM1[];   // 16384 floats = 64 KB (M1 only)
    #pragma unroll 1
    for (int i = threadIdx.x; i < M1_FLOATS; i += ETH) smM1[i] = g_M1[i];
    __syncthreads();

    int gid = blockIdx.x * ETH + threadIdx.x;
    int e0 = 2 * gid;
    if (e0 >= E) return;
    int e1 = e0 + 1;
    bool v1 = (e1 < E);
    int e1c = v1 ? e1 : e0;

    int r0 = ei[e0];
    int r1 = ei[e1c];
    float4 n0 = g_n[e0];
    float4 n1 = g_n[e1c];

    const float4* xp0 = (const float4*)(x + (size_t)r0 * 32);
    const float4* xp1 = (const float4*)(x + (size_t)r1 * 32);

    // scalar channels + q = xv.n for both edges
    float pa0[8], qa0[8], pa1[8], qa1[8];
    {
        float4 a = xp0[0], b = xp0[1];
        pa0[0]=a.x; pa0[1]=a.y; pa0[2]=a.z; pa0[3]=a.w;
        pa0[4]=b.x; pa0[5]=b.y; pa0[6]=b.z; pa0[7]=b.w;
        float4 A=xp0[2], B=xp0[3], C=xp0[4], D=xp0[5], Ee=xp0[6], F=xp0[7];
        qa0[0] = A.x*n0.x + A.y*n0.y + A.z*n0.z;
        qa0[1] = A.w*n0.x + B.x*n0.y + B.y*n0.z;
        qa0[2] = B.z*n0.x + B.w*n0.y + C.x*n0.z;
        qa0[3] = C.y*n0.x + C.z*n0.y + C.w*n0.z;
        qa0[4] = D.x*n0.x + D.y*n0.y + D.z*n0.z;
        qa0[5] = D.w*n0.x + Ee.x*n0.y + Ee.y*n0.z;
        qa0[6] = Ee.z*n0.x + Ee.w*n0.y + F.x*n0.z;
        qa0[7] = F.y*n0.x + F.z*n0.y + F.w*n0.z;
    }
    {
        float4 a = xp1[0], b = xp1[1];
        pa1[0]=a.x; pa1[1]=a.y; pa1[2]=a.z; pa1[3]=a.w;
        pa1[4]=b.x; pa1[5]=b.y; pa1[6]=b.z; pa1[7]=b.w;
        float4 A=xp1[2], B=xp1[3], C=xp1[4], D=xp1[5], Ee=xp1[6], F=xp1[7];
        qa1[0] = A.x*n1.x + A.y*n1.y + A.z*n1.z;
        qa1[1] = A.w*n1.x + B.x*n1.y + B.y*n1.z;
        qa1[2] = B.z*n1.x + B.w*n1.y + C.x*n1.z;
        qa1[3] = C.y*n1.x + C.z*n1.y + C.w*n1.z;
        qa1[4] = D.x*n1.x + D.y*n1.y + D.z*n1.z;
        qa1[5] = D.w*n1.x + Ee.x*n1.y + Ee.y*n1.z;
        qa1[6] = Ee.z*n1.x + Ee.w*n1.y + F.x*n1.z;
        qa1[7] = F.y*n1.x + F.z*n1.y + F.w*n1.z;
    }

    // ===== phase 1: sections A,B,C,E (smem) -> outS + cn =====
    ull outS0[4]={0,0,0,0}, outS1[4]={0,0,0,0};
    ull cn0[4]={0,0,0,0},   cn1[4]={0,0,0,0};

    #pragma unroll 1
    for (int ch = 0; ch < 8; ch++) {
        const float4* h40 = (const float4*)(g_hp[ch] + (size_t)e0 * 8);
        const float4* h41 = (const float4*)(g_hp[ch] + (size_t)e1c * 8);
        float4 ha = h40[0], hb = h40[1], hc = h41[0], hd = h41[1];
        ull hp0[8], hp1[8];
        hp0[0]=pk2(ha.x,ha.x); hp0[1]=pk2(ha.y,ha.y); hp0[2]=pk2(ha.z,ha.z); hp0[3]=pk2(ha.w,ha.w);
        hp0[4]=pk2(hb.x,hb.x); hp0[5]=pk2(hb.y,hb.y); hp0[6]=pk2(hb.z,hb.z); hp0[7]=pk2(hb.w,hb.w);
        hp1[0]=pk2(hc.x,hc.x); hp1[1]=pk2(hc.y,hc.y); hp1[2]=pk2(hc.z,hc.z); hp1[3]=pk2(hc.w,hc.w);
        hp1[4]=pk2(hd.x,hd.x); hp1[5]=pk2(hd.y,hd.y); hp1[6]=pk2(hd.z,hd.z); hp1[7]=pk2(hd.w,hd.w);

        const float* mb = smM1 + ch * 8 * 256;

        #pragma unroll
        for (int u = 0; u < 8; u++) {
            ull pp0 = pk2(pa0[u], pa0[u]);
            ull qq0 = pk2(qa0[u], qa0[u]);
            ull pp1 = pk2(pa1[u], pa1[u]);
            ull qq1 = pk2(qa1[u], qa1[u]);
            #pragma unroll
            for (int sect = 0; sect < 4; sect++) {
                ull a0=0,a1=0,a2=0,a3=0, b0=0,b1=0,b2=0,b3=0;
                #pragma unroll
                for (int mm = 0; mm < 8; mm++) {
                    const float* rp = mb + mm * 256 + sect * 64 + u * 8;
                    ulonglong2 t0 = *(const ulonglong2*)rp;
                    ulonglong2 t1 = *(const ulonglong2*)(rp + 4);
                    a0 = fma2(t0.x, hp0[mm], a0); a1 = fma2(t0.y, hp0[mm], a1);
                    a2 = fma2(t1.x, hp0[mm], a2); a3 = fma2(t1.y, hp0[mm], a3);
                    b0 = fma2(t0.x, hp1[mm], b0); b1 = fma2(t0.y, hp1[mm], b1);
                    b2 = fma2(t1.x, hp1[mm], b2); b3 = fma2(t1.y, hp1[mm], b3);
                }
                ull c0 = (sect & 1) ? qq0 : pp0;
                ull c1 = (sect & 1) ? qq1 : pp1;
                if (sect < 2) {
                    outS0[0]=fma2(a0,c0,outS0[0]); outS0[1]=fma2(a1,c0,outS0[1]);
                    outS0[2]=fma2(a2,c0,outS0[2]); outS0[3]=fma2(a3,c0,outS0[3]);
                    outS1[0]=fma2(b0,c1,outS1[0]); outS1[1]=fma2(b1,c1,outS1[1]);
                    outS1[2]=fma2(b2,c1,outS1[2]); outS1[3]=fma2(b3,c1,outS1[3]);
                } else {
                    cn0[0]=fma2(a0,c0,cn0[0]); cn0[1]=fma2(a1,c0,cn0[1]);
                    cn0[2]=fma2(a2,c0,cn0[2]); cn0[3]=fma2(a3,c0,cn0[3]);
                    cn1[0]=fma2(b0,c1,cn1[0]); cn1[1]=fma2(b1,c1,cn1[1]);
                    cn1[2]=fma2(b2,c1,cn1[2]); cn1[3]=fma2(b3,c1,cn1[3]);
                }
            }
        }
    }

    // scalar-output atomics (frees outS registers before phase 2)
    {
        double* y0 = g_acc + (size_t)r0 * 32;
        #pragma unroll
        for (int wp = 0; wp < 4; wp++) {
            float2 s = upk(outS0[wp]);
            atomicAdd(y0 + wp*2,     (double)s.x);
            atomicAdd(y0 + wp*2 + 1, (double)s.y);
        }
        if (v1) {
            double* y1 = g_acc + (size_t)r1 * 32;
            #pragma unroll
            for (int wp = 0; wp < 4; wp++) {
                float2 s = upk(outS1[wp]);
                atomicAdd(y1 + wp*2,     (double)s.x);
                atomicAdd(y1 + wp*2 + 1, (double)s.y);
            }
        }
    }

    // ===== phase 2: section D' (gmem/L1) -> outV, seeded with cn ⊗ n =====
    ull oV0[3][4], oV1[3][4];
    {
        ull nn;
        nn = pk2(n0.x, n0.x);
        oV0[0][0]=mul2(cn0[0],nn); oV0[0][1]=mul2(cn0[1],nn); oV0[0][2]=mul2(cn0[2],nn); oV0[0][3]=mul2(cn0[3],nn);
        nn = pk2(n0.y, n0.y);
        oV0[1][0]=mul2(cn0[0],nn); oV0[1][1]=mul2(cn0[1],nn); oV0[1][2]=mul2(cn0[2],nn); oV0[1][3]=mul2(cn0[3],nn);
        nn = pk2(n0.z, n0.z);
        oV0[2][0]=mul2(cn0[0],nn); oV0[2][1]=mul2(cn0[1],nn); oV0[2][2]=mul2(cn0[2],nn); oV0[2][3]=mul2(cn0[3],nn);
        nn = pk2(n1.x, n1.x);
        oV1[0][0]=mul2(cn1[0],nn); oV1[0][1]=mul2(cn1[1],nn); oV1[0][2]=mul2(cn1[2],nn); oV1[0][3]=mul2(cn1[3],nn);
        nn = pk2(n1.y, n1.y);
        oV1[1][0]=mul2(cn1[0],nn); oV1[1][1]=mul2(cn1[1],nn); oV1[1][2]=mul2(cn1[2],nn); oV1[1][3]=mul2(cn1[3],nn);
        nn = pk2(n1.z, n1.z);
        oV1[2][0]=mul2(cn1[0],nn); oV1[2][1]=mul2(cn1[1],nn); oV1[2][2]=mul2(cn1[2],nn); oV1[2][3]=mul2(cn1[3],nn);
    }

    #pragma unroll 1
    for (int pass = 0; pass < 2; pass++) {
        float4 A0 = xp0[2 + pass*3], B0 = xp0[3 + pass*3], C0 = xp0[4 + pass*3];
        float4 A1 = xp1[2 + pass*3], B1 = xp1[3 + pass*3], C1 = xp1[4 + pass*3];
        float xv0[4][3], xv1[4][3];
        xv0[0][0]=A0.x; xv0[0][1]=A0.y; xv0[0][2]=A0.z;
        xv0[1][0]=A0.w; xv0[1][1]=B0.x; xv0[1][2]=B0.y;
        xv0[2][0]=B0.z; xv0[2][1]=B0.w; xv0[2][2]=C0.x;
        xv0[3][0]=C0.y; xv0[3][1]=C0.z; xv0[3][2]=C0.w;
        xv1[0][0]=A1.x; xv1[0][1]=A1.y; xv1[0][2]=A1.z;
        xv1[1][0]=A1.w; xv1[1][1]=B1.x; xv1[1][2]=B1.y;
        xv1[2][0]=B1.z; xv1[2][1]=B1.w; xv1[2][2]=C1.x;
        xv1[3][0]=C1.y; xv1[3][1]=C1.z; xv1[3][2]=C1.w;

        #pragma unroll 1
        for (int ch = 0; ch < 8; ch++) {
            const float4* h40 = (const float4*)(g_hp[ch] + (size_t)e0 * 8);
            const float4* h41 = (const float4*)(g_hp[ch] + (size_t)e1c * 8);
            float4 ha = h40[0], hb = h40[1], hc = h41[0], hd = h41[1];
            ull hp0[8], hp1[8];
            hp0[0]=pk2(ha.x,ha.x); hp0[1]=pk2(ha.y,ha.y); hp0[2]=pk2(ha.z,ha.z); hp0[3]=pk2(ha.w,ha.w);
            hp0[4]=pk2(hb.x,hb.x); hp0[5]=pk2(hb.y,hb.y); hp0[6]=pk2(hb.z,hb.z); hp0[7]=pk2(hb.w,hb.w);
            hp1[0]=pk2(hc.x,hc.x); hp1[1]=pk2(hc.y,hc.y); hp1[2]=pk2(hc.z,hc.z); hp1[3]=pk2(hc.w,hc.w);
            hp1[4]=pk2(hd.x,hd.x); hp1[5]=pk2(hd.y,hd.y); hp1[6]=pk2(hd.z,hd.z); hp1[7]=pk2(hd.w,hd.w);

            const float* mb = g_M2 + ch * 8 * 64 + pass * 32;

            #pragma unroll
            for (int u = 0; u < 4; u++) {
                ull a0=0,a1=0,a2=0,a3=0, b0=0,b1=0,b2=0,b3=0;
                #pragma unroll
                for (int mm = 0; mm < 8; mm++) {
                    const float* rp = mb + mm * 64 + u * 8;
                    ulonglong2 t0 = __ldg((const ulonglong2*)rp);
                    ulonglong2 t1 = __ldg((const ulonglong2*)(rp + 4));
                    a0 = fma2(t0.x, hp0[mm], a0); a1 = fma2(t0.y, hp0[mm], a1);
                    a2 = fma2(t1.x, hp0[mm], a2); a3 = fma2(t1.y, hp0[mm], a3);
                    b0 = fma2(t0.x, hp1[mm], b0); b1 = fma2(t0.y, hp1[mm], b1);
                    b2 = fma2(t1.x, hp1[mm], b2); b3 = fma2(t1.y, hp1[mm], b3);
                }
                #pragma unroll
                for (int k = 0; k < 3; k++) {
                    ull x0 = pk2(xv0[u][k], xv0[u][k]);
                    ull x1 = pk2(xv1[u][k], xv1[u][k]);
                    oV0[k][0]=fma2(a0,x0,oV0[k][0]); oV0[k][1]=fma2(a1,x0,oV0[k][1]);
                    oV0[k][2]=fma2(a2,x0,oV0[k][2]); oV0[k][3]=fma2(a3,x0,oV0[k][3]);
                    oV1[k][0]=fma2(b0,x1,oV1[k][0]); oV1[k][1]=fma2(b1,x1,oV1[k][1]);
                    oV1[k][2]=fma2(b2,x1,oV1[k][2]); oV1[k][3]=fma2(b3,x1,oV1[k][3]);
                }
            }
        }
    }

    // vector-output atomics
    {
        double* y0 = g_acc + (size_t)r0 * 32;
        #pragma unroll
        for (int wp = 0; wp < 4; wp++) {
            #pragma unroll
            for (int k = 0; k < 3; k++) {
                float2 v = upk(oV0[k][wp]);
                atomicAdd(y0 + 8 + (wp*2)*3   + k, (double)v.x);
                atomicAdd(y0 + 8 + (wp*2+1)*3 + k, (double)v.y);
            }
        }
        if (v1) {
            double* y1 = g_acc + (size_t)r1 * 32;
            #pragma unroll
            for (int wp = 0; wp < 4; wp++) {
                #pragma unroll
                for (int k = 0; k < 3; k++) {
                    float2 v = upk(oV1[k][wp]);
                    atomicAdd(y1 + 8 + (wp*2)*3   + k, (double)v.x);
                    atomicAdd(y1 + 8 + (wp*2+1)*3 + k, (double)v.y);
                }
            }
        }
    }
}

extern "C" void kernel_launch(void* const* d_in, const int* in_sizes, int n_in,
                              void* d_out, int out_size)
{
    const float* x   = (const float*)d_in[0];
    const float* pos = (const float*)d_in[1];
    const int*   ei  = (const int*)d_in[2];
    const float* W1  = (const float*)d_in[3];
    const float* W2  = (const float*)d_in[4];
    float* out = (float*)d_out;

    int E = in_sizes[2] / 2;
    int N = in_sizes[1] / 3;

    prep_kernel<<<(M_FLOATS + 255) / 256, 256>>>(W1, W2);
    zero_acc_kernel<<<(N * 32 + 255) / 256, 256>>>(N * 32);
    h_kernel<<<(E + HTH - 1) / HTH, HTH>>>(pos, ei, E);

    int pairs = (E + 1) / 2;
    int blocks = (pairs + ETH - 1) / ETH;
    size_t smem = M1_FLOATS * sizeof(float);
    cudaFuncSetAttribute(edge_kernel, cudaFuncAttributeMaxDynamicSharedMemorySize, (int)smem);
    edge_kernel<<<blocks, ETH, smem>>>(x, ei, E);

    finish_kernel<<<(N * 32 + 255) / 256, 256>>>(out, N);
}